// round 6
// baseline (speedup 1.0000x reference)
#include <cuda_runtime.h>
#include <math.h>

#define B_DIM 256
#define V_DIM 50257
#define SEGS  8
#define SEG_LEN 6283                  // ceil(V/8) = 6283 (8*6283 = 50264 >= 50257)

// Partial sum-of-exp per row segment: [b*SEGS + seg]
__device__ float g_partial[SEGS * B_DIM];

// ---------------------------------------------------------------------------
// Kernel 1: PURE stats — branch-free partial sum-of-exp.
// 8 CTAs per row (2048 CTAs x 256 thr), ~3.1 elems/thread/accumulator.
// Scalar loads, 4 independent accumulators (R4's proven form, zeroing moved
// to a memset graph node).
// ---------------------------------------------------------------------------
__global__ __launch_bounds__(256)
void row_stats(const float* __restrict__ w) {
    const int bid = blockIdx.x;
    const int b   = bid >> 3;
    const int seg = bid & 7;
    const int vs  = seg * SEG_LEN;
    const int ve  = (vs + SEG_LEN < V_DIM) ? (vs + SEG_LEN) : V_DIM;
    const float* row = w + (size_t)b * V_DIM;

    float s0 = 0.f, s1 = 0.f, s2 = 0.f, s3 = 0.f;
    int v = vs + threadIdx.x;
    for (; v + 768 < ve; v += 1024) {
        const float x0 = __ldg(row + v);
        const float x1 = __ldg(row + v + 256);
        const float x2 = __ldg(row + v + 512);
        const float x3 = __ldg(row + v + 768);
        s0 += __expf(x0); s1 += __expf(x1);
        s2 += __expf(x2); s3 += __expf(x3);
    }
    for (; v < ve; v += 256) s0 += __expf(__ldg(row + v));

    float s = (s0 + s1) + (s2 + s3);
    #pragma unroll
    for (int o = 16; o > 0; o >>= 1)
        s += __shfl_xor_sync(0xFFFFFFFFu, s, o);

    __shared__ float ss[8];
    const int lane = threadIdx.x & 31;
    const int wid  = threadIdx.x >> 5;
    if (lane == 0) ss[wid] = s;
    __syncthreads();
    if (wid == 0) {
        s = (lane < 8) ? ss[lane] : 0.0f;
        #pragma unroll
        for (int o = 4; o > 0; o >>= 1)
            s += __shfl_xor_sync(0xFFFFFFFFu, s, o);
        if (lane == 0) g_partial[bid] = s;
    }
}

__device__ __forceinline__ float row_inv(int b) {
    float t = 0.f;
    #pragma unroll
    for (int k = 0; k < SEGS; k++) t += __ldg(&g_partial[SEGS * b + k]);
    return 1.0f / t;
}

// ---------------------------------------------------------------------------
// Kernel 2 (fused, at the L2-atomic wall): weights + scatter-add +
// transposed write. 32b x 128v tiles, block (32,32), 4 v-elems/thread.
// wT store via __stwt (write-through): keeps wT's 51 MB out of L2 so the
// avg atomics and w re-reads get the capacity/bandwidth.
// ---------------------------------------------------------------------------
__global__ __launch_bounds__(1024)
void weights_scatter_transpose(const int*   __restrict__ idx,
                               const float* __restrict__ w,
                               float*       __restrict__ avg,
                               float*       __restrict__ wT) {
    __shared__ float4 tile[32][32];

    const int vt = blockIdx.x;
    const int bt = blockIdx.y;
    const int tx = threadIdx.x;
    const int ty = threadIdx.y;

    const int b = bt * 32 + ty;
    const size_t rowoff = (size_t)b * V_DIM;
    const float inv = row_inv(b);

    const int vbase = vt * 128 + tx * 4;
    const bool full = (vbase + 3) < V_DIM;

    if (full) {
        float x[4]; int id[4];
        #pragma unroll
        for (int k = 0; k < 4; k++) x[k]  = __ldg(w + rowoff + vbase + k);
        #pragma unroll
        for (int k = 0; k < 4; k++) id[k] = __ldcs(idx + rowoff + vbase + k);

        float4 wv;
        #pragma unroll
        for (int k = 0; k < 4; k++) {
            const float e = __expf(x[k]) * inv;
            ((float*)&wv)[k] = e;
            atomicAdd(&avg[rowoff + id[k]], e);     // no-return -> REDG
        }
        tile[ty][tx ^ (ty >> 2)] = wv;
    } else {
        float4 wv;
        #pragma unroll
        for (int k = 0; k < 4; k++) {
            const int v = vbase + k;
            float e = 0.0f;
            if (v < V_DIM) {
                e = __expf(__ldg(w + rowoff + v)) * inv;
                atomicAdd(&avg[rowoff + __ldcs(idx + rowoff + v)], e);
            }
            ((float*)&wv)[k] = e;
        }
        tile[ty][tx ^ (ty >> 2)] = wv;
    }
    __syncthreads();

    const int t = ty * 32 + tx;
    const int r = t >> 3;
    const int c = t & 7;
    const int v = vt * 128 + r;
    if (v < V_DIM) {
        const int wq  = r >> 2;
        const int sub = r & 3;
        float4 o;
        #pragma unroll
        for (int j = 0; j < 4; j++)
            ((float*)&o)[j] = ((const float*)&tile[c * 4 + j][wq ^ c])[sub];
        __stwt((float4*)&wT[(size_t)v * B_DIM + bt * 32 + c * 4], o);
    }
}

// ---------------------------------------------------------------------------
extern "C" void kernel_launch(void* const* d_in, const int* in_sizes, int n_in,
                              void* d_out, int out_size) {
    const int*   indices = (const int*)d_in[0];
    const float* w_es    = (const float*)d_in[1];

    float* avg = (float*)d_out;                           // [B, V]
    float* wT  = (float*)d_out + (size_t)B_DIM * V_DIM;   // [V, B]

    // Zero the avg region with a memset node (graph-capturable, near
    // write-peak) instead of burning K1 load-loop slots on it.
    cudaMemsetAsync(avg, 0, (size_t)B_DIM * V_DIM * sizeof(float));

    row_stats<<<SEGS * B_DIM, 256>>>(w_es);

    dim3 grid((V_DIM + 127) / 128, B_DIM / 32);  // 393 x 8
    dim3 block(32, 32);
    weights_scatter_transpose<<<grid, block>>>(indices, w_es, avg, wT);
}

// round 7
// speedup vs baseline: 1.0903x; 1.0903x over previous
#include <cuda_runtime.h>
#include <math.h>

#define B_DIM 256
#define V_DIM 50257
#define SEGS  4
#define SEG_LEN 12565                 // ceil(V/4)
#define N4_AVG ((B_DIM * V_DIM) / 4)

// Partial sum-of-exp per row segment: [b*SEGS + seg]
__device__ float g_partial[SEGS * B_DIM];

// ---------------------------------------------------------------------------
// Kernel 1: partial sum-of-exp (stats FIRST: w loads start at cycle 0),
// then zero the avg region (stores fill idle slots while sums drain).
// 4 CTAs/row, 256 thr. 8 batched loads per iter -> 2x MLP vs R3.
// ---------------------------------------------------------------------------
__global__ __launch_bounds__(256)
void stats_and_zero(const float* __restrict__ w, float4* __restrict__ avg4) {
    const int bid = blockIdx.x;
    const int b   = bid >> 2;
    const int seg = bid & 3;
    const int vs  = seg * SEG_LEN;
    const int ve  = (vs + SEG_LEN < V_DIM) ? (vs + SEG_LEN) : V_DIM;
    const float* row = w + (size_t)b * V_DIM;

    float s0 = 0.f, s1 = 0.f, s2 = 0.f, s3 = 0.f;
    int v = vs + threadIdx.x;
    for (; v + 7 * 256 < ve; v += 8 * 256) {
        float x0 = __ldg(row + v);
        float x1 = __ldg(row + v + 1 * 256);
        float x2 = __ldg(row + v + 2 * 256);
        float x3 = __ldg(row + v + 3 * 256);
        float x4 = __ldg(row + v + 4 * 256);
        float x5 = __ldg(row + v + 5 * 256);
        float x6 = __ldg(row + v + 6 * 256);
        float x7 = __ldg(row + v + 7 * 256);
        s0 += __expf(x0); s1 += __expf(x1);
        s2 += __expf(x2); s3 += __expf(x3);
        s0 += __expf(x4); s1 += __expf(x5);
        s2 += __expf(x6); s3 += __expf(x7);
    }
    for (; v < ve; v += 256) s0 += __expf(__ldg(row + v));

    // --- zero share of avg (after stats loads are all in flight) ---
    {
        const float4 z = make_float4(0.f, 0.f, 0.f, 0.f);
        const int stride = gridDim.x * blockDim.x;
        for (int i = bid * blockDim.x + threadIdx.x; i < N4_AVG; i += stride)
            avg4[i] = z;
    }

    float s = (s0 + s1) + (s2 + s3);
    #pragma unroll
    for (int o = 16; o > 0; o >>= 1)
        s += __shfl_xor_sync(0xFFFFFFFFu, s, o);

    __shared__ float ss[8];
    const int lane = threadIdx.x & 31;
    const int wid  = threadIdx.x >> 5;
    if (lane == 0) ss[wid] = s;
    __syncthreads();
    if (wid == 0) {
        s = (lane < 8) ? ss[lane] : 0.0f;
        #pragma unroll
        for (int o = 4; o > 0; o >>= 1)
            s += __shfl_xor_sync(0xFFFFFFFFu, s, o);
        if (lane == 0) g_partial[bid] = s;
    }
}

// ---------------------------------------------------------------------------
// Kernel 2 (R3's proven 81.2us version, byte-identical): weights +
// scatter-add + transposed write. 32b x 128v tiles, block (32,32).
// ---------------------------------------------------------------------------
__global__ __launch_bounds__(1024)
void weights_scatter_transpose(const int*   __restrict__ idx,
                               const float* __restrict__ w,
                               float*       __restrict__ avg,
                               float*       __restrict__ wT) {
    __shared__ float4 tile[32][32];

    const int vt = blockIdx.x;
    const int bt = blockIdx.y;
    const int tx = threadIdx.x;
    const int ty = threadIdx.y;

    const int b = bt * 32 + ty;
    const size_t rowoff = (size_t)b * V_DIM;
    const float inv = 1.0f / (__ldg(&g_partial[4 * b + 0]) + __ldg(&g_partial[4 * b + 1]) +
                              __ldg(&g_partial[4 * b + 2]) + __ldg(&g_partial[4 * b + 3]));

    const int vbase = vt * 128 + tx * 4;
    const bool full = (vbase + 3) < V_DIM;

    if (full) {
        float x[4]; int id[4];
        #pragma unroll
        for (int k = 0; k < 4; k++) x[k]  = __ldg(w + rowoff + vbase + k);
        #pragma unroll
        for (int k = 0; k < 4; k++) id[k] = __ldcs(idx + rowoff + vbase + k);

        float4 wv;
        #pragma unroll
        for (int k = 0; k < 4; k++) {
            const float e = __expf(x[k]) * inv;
            ((float*)&wv)[k] = e;
            atomicAdd(&avg[rowoff + id[k]], e);     // no-return -> REDG
        }
        tile[ty][tx ^ (ty >> 2)] = wv;
    } else {
        float4 wv;
        #pragma unroll
        for (int k = 0; k < 4; k++) {
            const int v = vbase + k;
            float e = 0.0f;
            if (v < V_DIM) {
                e = __expf(__ldg(w + rowoff + v)) * inv;
                atomicAdd(&avg[rowoff + __ldcs(idx + rowoff + v)], e);
            }
            ((float*)&wv)[k] = e;
        }
        tile[ty][tx ^ (ty >> 2)] = wv;
    }
    __syncthreads();

    const int t = ty * 32 + tx;
    const int r = t >> 3;
    const int c = t & 7;
    const int v = vt * 128 + r;
    if (v < V_DIM) {
        const int wq  = r >> 2;
        const int sub = r & 3;
        float4 o;
        #pragma unroll
        for (int j = 0; j < 4; j++)
            ((float*)&o)[j] = ((const float*)&tile[c * 4 + j][wq ^ c])[sub];
        __stcs((float4*)&wT[(size_t)v * B_DIM + bt * 32 + c * 4], o);
    }
}

// ---------------------------------------------------------------------------
extern "C" void kernel_launch(void* const* d_in, const int* in_sizes, int n_in,
                              void* d_out, int out_size) {
    const int*   indices = (const int*)d_in[0];
    const float* w_es    = (const float*)d_in[1];

    float* avg = (float*)d_out;                           // [B, V]
    float* wT  = (float*)d_out + (size_t)B_DIM * V_DIM;   // [V, B]

    stats_and_zero<<<SEGS * B_DIM, 256>>>(w_es, (float4*)avg);

    dim3 grid((V_DIM + 127) / 128, B_DIM / 32);  // 393 x 8
    dim3 block(32, 32);
    weights_scatter_transpose<<<grid, block>>>(indices, w_es, avg, wT);
}

// round 8
// speedup vs baseline: 1.1113x; 1.0193x over previous
#include <cuda_runtime.h>
#include <math.h>

#define B_DIM 256
#define V_DIM 50257
#define SEGS  4
#define SEG_LEN 12565                 // ceil(V/4)
#define N_BIN 32                      // rows handled by smem binning (= bt 0)
#define ZERO_START4 ((N_BIN * V_DIM) / 4)            // 402,056 (exact)
#define N4_AVG      ((B_DIM * V_DIM) / 4)            // 3,216,448

// Partial sum-of-exp per row segment: [b*SEGS + seg]
__device__ float g_partial[SEGS * B_DIM];

// ---------------------------------------------------------------------------
// Kernel 1: stats (first: w loads start at cycle 0) + zero rows >= N_BIN
// (bin rows are fully overwritten by the bin kernel -> no zeroing needed).
// ---------------------------------------------------------------------------
__global__ __launch_bounds__(256)
void stats_and_zero(const float* __restrict__ w, float4* __restrict__ avg4) {
    const int bid = blockIdx.x;
    const int b   = bid >> 2;
    const int seg = bid & 3;
    const int vs  = seg * SEG_LEN;
    const int ve  = (vs + SEG_LEN < V_DIM) ? (vs + SEG_LEN) : V_DIM;
    const float* row = w + (size_t)b * V_DIM;

    float s0 = 0.f, s1 = 0.f, s2 = 0.f, s3 = 0.f;
    int v = vs + threadIdx.x;
    for (; v + 7 * 256 < ve; v += 8 * 256) {
        float x0 = __ldg(row + v);
        float x1 = __ldg(row + v + 1 * 256);
        float x2 = __ldg(row + v + 2 * 256);
        float x3 = __ldg(row + v + 3 * 256);
        float x4 = __ldg(row + v + 4 * 256);
        float x5 = __ldg(row + v + 5 * 256);
        float x6 = __ldg(row + v + 6 * 256);
        float x7 = __ldg(row + v + 7 * 256);
        s0 += __expf(x0); s1 += __expf(x1);
        s2 += __expf(x2); s3 += __expf(x3);
        s0 += __expf(x4); s1 += __expf(x5);
        s2 += __expf(x6); s3 += __expf(x7);
    }
    for (; v < ve; v += 256) s0 += __expf(__ldg(row + v));

    // zero share of avg rows [N_BIN, 256) while sums drain
    {
        const float4 z = make_float4(0.f, 0.f, 0.f, 0.f);
        const int stride = gridDim.x * blockDim.x;
        for (int i = ZERO_START4 + bid * blockDim.x + threadIdx.x; i < N4_AVG; i += stride)
            avg4[i] = z;
    }

    float s = (s0 + s1) + (s2 + s3);
    #pragma unroll
    for (int o = 16; o > 0; o >>= 1)
        s += __shfl_xor_sync(0xFFFFFFFFu, s, o);

    __shared__ float ss[8];
    const int lane = threadIdx.x & 31;
    const int wid  = threadIdx.x >> 5;
    if (lane == 0) ss[wid] = s;
    __syncthreads();
    if (wid == 0) {
        s = (lane < 8) ? ss[lane] : 0.0f;
        #pragma unroll
        for (int o = 4; o > 0; o >>= 1)
            s += __shfl_xor_sync(0xFFFFFFFFu, s, o);
        if (lane == 0) g_partial[bid] = s;
    }
}

__device__ __forceinline__ float row_inv(int b) {
    return 1.0f / (__ldg(&g_partial[4 * b + 0]) + __ldg(&g_partial[4 * b + 1]) +
                   __ldg(&g_partial[4 * b + 2]) + __ldg(&g_partial[4 * b + 3]));
}

// ---------------------------------------------------------------------------
// Bin kernel: one CTA per row b in [0, N_BIN). Accumulates the whole row in
// a 201KB shared bin table (ATOMS - SM-local, zero LTS atomic traffic),
// then streams the finished row out with plain stores.
// ---------------------------------------------------------------------------
__global__ __launch_bounds__(1024)
void bin_rows(const int*   __restrict__ idx,
              const float* __restrict__ w,
              float*       __restrict__ avg) {
    extern __shared__ float bins[];     // V_DIM floats
    const int b = blockIdx.x;
    const size_t rowoff = (size_t)b * V_DIM;
    const float inv = row_inv(b);

    for (int j = threadIdx.x; j < V_DIM; j += 1024) bins[j] = 0.0f;
    __syncthreads();

    int i = threadIdx.x;
    for (; i + 3 * 1024 < V_DIM; i += 4 * 1024) {
        float x0 = __ldcs(w + rowoff + i);
        float x1 = __ldcs(w + rowoff + i + 1024);
        float x2 = __ldcs(w + rowoff + i + 2048);
        float x3 = __ldcs(w + rowoff + i + 3072);
        int i0 = __ldcs(idx + rowoff + i);
        int i1 = __ldcs(idx + rowoff + i + 1024);
        int i2 = __ldcs(idx + rowoff + i + 2048);
        int i3 = __ldcs(idx + rowoff + i + 3072);
        atomicAdd(&bins[i0], __expf(x0) * inv);
        atomicAdd(&bins[i1], __expf(x1) * inv);
        atomicAdd(&bins[i2], __expf(x2) * inv);
        atomicAdd(&bins[i3], __expf(x3) * inv);
    }
    for (; i < V_DIM; i += 1024)
        atomicAdd(&bins[__ldcs(idx + rowoff + i)], __expf(__ldcs(w + rowoff + i)) * inv);
    __syncthreads();

    for (int j = threadIdx.x; j < V_DIM; j += 1024)
        __stcs(&avg[rowoff + j], bins[j]);
}

// ---------------------------------------------------------------------------
// Tile kernel: scatter-add (rows >= N_BIN only) + transposed write (ALL rows).
// Identical to the proven 81us kernel except bt==0 skips the atomics.
// ---------------------------------------------------------------------------
__global__ __launch_bounds__(1024)
void weights_scatter_transpose(const int*   __restrict__ idx,
                               const float* __restrict__ w,
                               float*       __restrict__ avg,
                               float*       __restrict__ wT) {
    __shared__ float4 tile[32][32];

    const int vt = blockIdx.x;
    const int bt = blockIdx.y;
    const int tx = threadIdx.x;
    const int ty = threadIdx.y;
    const bool doScatter = (bt != 0);   // bt 0 rows handled by bin_rows

    const int b = bt * 32 + ty;
    const size_t rowoff = (size_t)b * V_DIM;
    const float inv = row_inv(b);

    const int vbase = vt * 128 + tx * 4;
    const bool full = (vbase + 3) < V_DIM;

    if (full) {
        float x[4]; int id[4];
        #pragma unroll
        for (int k = 0; k < 4; k++) x[k]  = __ldg(w + rowoff + vbase + k);
        #pragma unroll
        for (int k = 0; k < 4; k++) id[k] = __ldcs(idx + rowoff + vbase + k);

        float4 wv;
        #pragma unroll
        for (int k = 0; k < 4; k++) {
            const float e = __expf(x[k]) * inv;
            ((float*)&wv)[k] = e;
            if (doScatter) atomicAdd(&avg[rowoff + id[k]], e);  // REDG
        }
        tile[ty][tx ^ (ty >> 2)] = wv;
    } else {
        float4 wv;
        #pragma unroll
        for (int k = 0; k < 4; k++) {
            const int v = vbase + k;
            float e = 0.0f;
            if (v < V_DIM) {
                e = __expf(__ldg(w + rowoff + v)) * inv;
                if (doScatter) atomicAdd(&avg[rowoff + __ldcs(idx + rowoff + v)], e);
            }
            ((float*)&wv)[k] = e;
        }
        tile[ty][tx ^ (ty >> 2)] = wv;
    }
    __syncthreads();

    const int t = ty * 32 + tx;
    const int r = t >> 3;
    const int c = t & 7;
    const int v = vt * 128 + r;
    if (v < V_DIM) {
        const int wq  = r >> 2;
        const int sub = r & 3;
        float4 o;
        #pragma unroll
        for (int j = 0; j < 4; j++)
            ((float*)&o)[j] = ((const float*)&tile[c * 4 + j][wq ^ c])[sub];
        __stcs((float4*)&wT[(size_t)v * B_DIM + bt * 32 + c * 4], o);
    }
}

// ---------------------------------------------------------------------------
extern "C" void kernel_launch(void* const* d_in, const int* in_sizes, int n_in,
                              void* d_out, int out_size) {
    const int*   indices = (const int*)d_in[0];
    const float* w_es    = (const float*)d_in[1];

    float* avg = (float*)d_out;                           // [B, V]
    float* wT  = (float*)d_out + (size_t)B_DIM * V_DIM;   // [V, B]

    // Side stream + events for the fork (host objects only; no device memory).
    // Created fresh per call (kernel_launch runs only twice), never destroyed.
    cudaStream_t s2;
    cudaEvent_t  eF, eJ;
    cudaStreamCreateWithFlags(&s2, cudaStreamNonBlocking);
    cudaEventCreateWithFlags(&eF, cudaEventDisableTiming);
    cudaEventCreateWithFlags(&eJ, cudaEventDisableTiming);
    cudaFuncSetAttribute(bin_rows, cudaFuncAttributeMaxDynamicSharedMemorySize,
                         V_DIM * sizeof(float));

    stats_and_zero<<<SEGS * B_DIM, 256>>>(w_es, (float4*)avg);

    // Fork: bin_rows on s2 runs CONCURRENT with the tile kernel.
    cudaEventRecord(eF, 0);
    cudaStreamWaitEvent(s2, eF, 0);
    bin_rows<<<N_BIN, 1024, V_DIM * sizeof(float), s2>>>(indices, w_es, avg);
    cudaEventRecord(eJ, s2);

    dim3 grid((V_DIM + 127) / 128, B_DIM / 32);  // 393 x 8
    dim3 block(32, 32);
    weights_scatter_transpose<<<grid, block>>>(indices, w_es, avg, wT);

    // Join.
    cudaStreamWaitEvent(0, eJ, 0);
}